// round 1
// baseline (speedup 1.0000x reference)
#include <cuda_runtime.h>

typedef unsigned long long u64;
#define DEV __device__ __forceinline__

static constexpr int Bb   = 2;
static constexpr int Ls   = 2048;
static constexpr int DM   = 768;
static constexpr int Hh   = 12;
static constexpr int FEAT = 16;
static constexpr int HD   = 64;
static constexpr int NR   = Bb * Ls;   // 4096 total rows

// scratch (device globals; no allocation allowed)
__device__ float g_q[NR * Hh * FEAT];  // [n][h*16+f]
__device__ float g_k[NR * Hh * FEAT];
__device__ float g_v[NR * DM];         // [n][h*64+e]
__device__ float g_y[NR * DM];         // attention output, [n][h*64+e]

// ---------------- f32x2 helpers (packed fp32 pairs, 2x FFMA throughput) ---
DEV u64 pack2(float lo, float hi) {
    u64 r; asm("mov.b64 %0, {%1, %2};" : "=l"(r) : "f"(lo), "f"(hi)); return r;
}
DEV void unpack2(u64 v, float &lo, float &hi) {
    asm("mov.b64 {%0, %1}, %2;" : "=f"(lo), "=f"(hi) : "l"(v));
}
DEV u64 fma2(u64 a, u64 b, u64 c) {
    u64 d; asm("fma.rn.f32x2 %0, %1, %2, %3;" : "=l"(d) : "l"(a), "l"(b), "l"(c));
    return d;
}

// ---------------- NT GEMM: Y[n,o] = sum_d X[n,d] * W[o,d] ------------------
// X: [N,768] row-major, W: [Dout,768] row-major, Y: [N,Dout].
// Block tile 128(n) x 64(o), 128 threads, 8x8 micro-tile, f32x2 packed along o.
__global__ __launch_bounds__(128) void gemm_nt(const float* __restrict__ X,
                                               const float* __restrict__ W,
                                               float* __restrict__ Y,
                                               int Dout)
{
    __shared__ float XsT[16][128];   // [d][n] transposed
    __shared__ float WsT[16][64];    // [d][o] transposed

    const int t  = threadIdx.x;
    const int nb = blockIdx.x, ob = blockIdx.y;
    const int tr = t >> 3;           // 0..15  -> rows n0 = 8*tr
    const int te = t & 7;            // 0..7   -> o groups {4*te.., 32+4*te..}
    const int n0 = tr * 8;

    u64 acc[8][2][2];
    #pragma unroll
    for (int i = 0; i < 8; i++)
        #pragma unroll
        for (int jj = 0; jj < 2; jj++)
            #pragma unroll
            for (int j = 0; j < 2; j++) acc[i][jj][j] = 0ull;

    const float* Xb = X + (size_t)nb * 128 * DM;
    const float* Wb = W + (size_t)ob * 64 * DM;

    for (int d0 = 0; d0 < DM; d0 += 16) {
        __syncthreads();
        // fill XsT (128 rows x 16 d): 512 float4, 4 per thread
        #pragma unroll
        for (int r = 0; r < 4; r++) {
            int i = t + 128 * r;
            int n = i >> 2, dj = i & 3;
            float4 v = *(const float4*)(Xb + n * DM + d0 + dj * 4);
            XsT[dj*4+0][n] = v.x; XsT[dj*4+1][n] = v.y;
            XsT[dj*4+2][n] = v.z; XsT[dj*4+3][n] = v.w;
        }
        // fill WsT (64 rows x 16 d): 256 float4, 2 per thread
        #pragma unroll
        for (int r = 0; r < 2; r++) {
            int i = t + 128 * r;
            int o = i >> 2, dj = i & 3;
            float4 v = *(const float4*)(Wb + o * DM + d0 + dj * 4);
            WsT[dj*4+0][o] = v.x; WsT[dj*4+1][o] = v.y;
            WsT[dj*4+2][o] = v.z; WsT[dj*4+3][o] = v.w;
        }
        __syncthreads();

        #pragma unroll
        for (int d = 0; d < 16; d++) {
            float4 a0 = *(const float4*)&XsT[d][n0];
            float4 a1 = *(const float4*)&XsT[d][n0 + 4];
            u64 as[8];
            as[0] = pack2(a0.x, a0.x); as[1] = pack2(a0.y, a0.y);
            as[2] = pack2(a0.z, a0.z); as[3] = pack2(a0.w, a0.w);
            as[4] = pack2(a1.x, a1.x); as[5] = pack2(a1.y, a1.y);
            as[6] = pack2(a1.z, a1.z); as[7] = pack2(a1.w, a1.w);
            u64 b00 = *(const u64*)&WsT[d][te * 4];
            u64 b01 = *(const u64*)&WsT[d][te * 4 + 2];
            u64 b10 = *(const u64*)&WsT[d][32 + te * 4];
            u64 b11 = *(const u64*)&WsT[d][32 + te * 4 + 2];
            #pragma unroll
            for (int i = 0; i < 8; i++) {
                acc[i][0][0] = fma2(as[i], b00, acc[i][0][0]);
                acc[i][0][1] = fma2(as[i], b01, acc[i][0][1]);
                acc[i][1][0] = fma2(as[i], b10, acc[i][1][0]);
                acc[i][1][1] = fma2(as[i], b11, acc[i][1][1]);
            }
        }
    }

    #pragma unroll
    for (int i = 0; i < 8; i++) {
        int n = nb * 128 + n0 + i;
        float* Yr = Y + (size_t)n * Dout + ob * 64;
        #pragma unroll
        for (int jj = 0; jj < 2; jj++)
            #pragma unroll
            for (int j = 0; j < 2; j++) {
                float lo, hi; unpack2(acc[i][jj][j], lo, hi);
                int o = jj * 32 + te * 4 + j * 2;
                Yr[o] = lo; Yr[o + 1] = hi;
            }
    }
}

// ---------------- fused Based attention --------------------------------
// Per (b,h): w[n,m] = (1 + s/4 + s^2/32) * (m<=n ? 2 : 1), s = q_n . k_m (16d)
// y[n] = (sum_m w * v_m) / (sum_m w)
// Grid: (L/128 row tiles, B*H). 128 threads.
__global__ __launch_bounds__(128) void attn_kernel()
{
    __shared__ float Ks[32][16];
    __shared__ float Vs[32][64];
    __shared__ float Ws[32][128];   // w tile, [m][n]
    __shared__ float denom_s[128];

    const int t  = threadIdx.x;
    const int rb = blockIdx.x;
    const int bh = blockIdx.y;
    const int b = bh / Hh, h = bh % Hh;

    const int row = rb * 128 + t;   // phase-A row (seq position)

    // q row -> packed registers
    const float* qp = g_q + ((size_t)(b * Ls + row)) * (Hh * FEAT) + h * FEAT;
    u64 q2[8];
    #pragma unroll
    for (int j = 0; j < 4; j++) {
        float4 v = *(const float4*)(qp + 4 * j);
        q2[2*j]   = pack2(v.x, v.y);
        q2[2*j+1] = pack2(v.z, v.w);
    }
    denom_s[t] = 0.0f;

    const int tr = t >> 3, te = t & 7;   // phase-B mapping
    u64 acc[8][2][2];
    #pragma unroll
    for (int i = 0; i < 8; i++)
        #pragma unroll
        for (int jj = 0; jj < 2; jj++)
            #pragma unroll
            for (int j = 0; j < 2; j++) acc[i][jj][j] = 0ull;

    const float* kbase = g_k + ((size_t)(b * Ls)) * (Hh * FEAT) + h * FEAT;
    const float* vbase = g_v + ((size_t)(b * Ls)) * DM + h * HD;

    for (int mt = 0; mt < Ls / 32; mt++) {
        __syncthreads();
        // fill K tile: 32x16 = 128 float4, one per thread
        {
            int m = t >> 2, dj = t & 3;
            float4 v = *(const float4*)(kbase + (size_t)(mt * 32 + m) * (Hh * FEAT) + dj * 4);
            *(float4*)&Ks[m][dj * 4] = v;
        }
        // fill V tile: 32x64 = 512 float4, four per thread
        #pragma unroll
        for (int r = 0; r < 4; r++) {
            int i = t + 128 * r;
            int m = i >> 4, dj = i & 15;
            float4 v = *(const float4*)(vbase + (size_t)(mt * 32 + m) * DM + dj * 4);
            *(float4*)&Vs[m][dj * 4] = v;
        }
        __syncthreads();

        // ---- phase A: scores for this thread's row over 32 m ----
        float dsum = 0.0f;
        #pragma unroll 8
        for (int m = 0; m < 32; m++) {
            const u64* kr = (const u64*)&Ks[m][0];
            u64 s2 = 0ull;
            #pragma unroll
            for (int j = 0; j < 8; j++) s2 = fma2(q2[j], kr[j], s2);
            float lo, hi; unpack2(s2, lo, hi);
            float s = lo + hi;
            float a = fmaf(s, fmaf(s, 0.03125f, 0.25f), 1.0f);
            int mg = mt * 32 + m;
            float w = (mg <= row) ? (a + a) : a;
            Ws[m][t] = w;
            dsum += w;
        }
        denom_s[t] += dsum;
        __syncthreads();

        // ---- phase B: acc += w * V  (128n x 64e x 32m GEMM) ----
        #pragma unroll 8
        for (int m = 0; m < 32; m++) {
            float4 w0 = *(const float4*)&Ws[m][8 * tr];
            float4 w1 = *(const float4*)&Ws[m][8 * tr + 4];
            u64 ws[8];
            ws[0] = pack2(w0.x, w0.x); ws[1] = pack2(w0.y, w0.y);
            ws[2] = pack2(w0.z, w0.z); ws[3] = pack2(w0.w, w0.w);
            ws[4] = pack2(w1.x, w1.x); ws[5] = pack2(w1.y, w1.y);
            ws[6] = pack2(w1.z, w1.z); ws[7] = pack2(w1.w, w1.w);
            u64 b00 = *(const u64*)&Vs[m][4 * te];
            u64 b01 = *(const u64*)&Vs[m][4 * te + 2];
            u64 b10 = *(const u64*)&Vs[m][32 + 4 * te];
            u64 b11 = *(const u64*)&Vs[m][32 + 4 * te + 2];
            #pragma unroll
            for (int i = 0; i < 8; i++) {
                acc[i][0][0] = fma2(ws[i], b00, acc[i][0][0]);
                acc[i][0][1] = fma2(ws[i], b01, acc[i][0][1]);
                acc[i][1][0] = fma2(ws[i], b10, acc[i][1][0]);
                acc[i][1][1] = fma2(ws[i], b11, acc[i][1][1]);
            }
        }
    }
    __syncthreads();

    // epilogue: y = acc / denom, write to g_y[n][h*64+e]
    float* ybase = g_y + ((size_t)(b * Ls + rb * 128)) * DM + h * HD;
    #pragma unroll
    for (int i = 0; i < 8; i++) {
        int n = 8 * tr + i;
        float rz = 1.0f / denom_s[n];
        float* yr = ybase + (size_t)n * DM;
        #pragma unroll
        for (int jj = 0; jj < 2; jj++)
            #pragma unroll
            for (int j = 0; j < 2; j++) {
                float lo, hi; unpack2(acc[i][jj][j], lo, hi);
                int e = jj * 32 + te * 4 + j * 2;
                yr[e]     = lo * rz;
                yr[e + 1] = hi * rz;
            }
    }
}

// ---------------- launcher ------------------------------------------------
extern "C" void kernel_launch(void* const* d_in, const int* in_sizes, int n_in,
                              void* d_out, int out_size)
{
    const float* hs = (const float*)d_in[0];
    const float* Wq = (const float*)d_in[1];
    const float* Wk = (const float*)d_in[2];
    const float* Wv = (const float*)d_in[3];
    const float* Wo = (const float*)d_in[4];
    float* out = (float*)d_out;

    float *pq, *pk, *pv, *py;
    cudaGetSymbolAddress((void**)&pq, g_q);
    cudaGetSymbolAddress((void**)&pk, g_k);
    cudaGetSymbolAddress((void**)&pv, g_v);
    cudaGetSymbolAddress((void**)&py, g_y);

    dim3 blk(128);
    // q,k projections: [4096,768] x [192,768]^T
    gemm_nt<<<dim3(NR / 128, (Hh * FEAT) / 64), blk>>>(hs, Wq, pq, Hh * FEAT);
    gemm_nt<<<dim3(NR / 128, (Hh * FEAT) / 64), blk>>>(hs, Wk, pk, Hh * FEAT);
    // v projection: [4096,768] x [768,768]^T
    gemm_nt<<<dim3(NR / 128, DM / 64), blk>>>(hs, Wv, pv, DM);
    // fused attention
    attn_kernel<<<dim3(Ls / 128, Bb * Hh), blk>>>();
    // output projection: [4096,768] x [768,768]^T
    gemm_nt<<<dim3(NR / 128, DM / 64), blk>>>(py, Wo, out, DM);
}